// round 15
// baseline (speedup 1.0000x reference)
#include <cuda_runtime.h>
#include <cstdint>

// out[b,c,i,j] = x[b,c, i^3, j^3]   (H = W = 256)
// j^3 within an aligned float4 = lane reverse; i^3 = row shuffle.
//
// R14: TPB=128 (last unsampled CTA shape; 256 and 512 measured neutral
// vs each other). UNROLL=8 front-batched LDG.128 (MLP saturation point),
// streaming cache hints, decomposed index math (fused XOR form regresses),
// non-persistent consecutive-blockIdx waves (persistent regresses via TLB).

static constexpr int W4 = 64;    // float4s per row
static constexpr int H  = 256;
static constexpr int UNROLL = 8;
static constexpr int TPB = 128;

__global__ void __launch_bounds__(TPB)
dualswitch_kernel(const float4* __restrict__ in, float4* __restrict__ out) {
    // Each block owns a contiguous chunk of TPB*UNROLL float4s.
    int base = blockIdx.x * (TPB * UNROLL) + threadIdx.x;

    float4 v[UNROLL];
    #pragma unroll
    for (int u = 0; u < UNROLL; u++) {
        int idx  = base + u * TPB;
        int g    = idx & (W4 - 1);
        int rest = idx >> 6;
        int i    = rest & (H - 1);
        int bc   = rest >> 8;
        int in_idx = ((bc << 8) | (i ^ 3)) * W4 + g;
        v[u] = __ldcs(in + in_idx);
    }

    #pragma unroll
    for (int u = 0; u < UNROLL; u++) {
        int idx = base + u * TPB;
        __stcs(out + idx, make_float4(v[u].w, v[u].z, v[u].y, v[u].x));
    }
}

extern "C" void kernel_launch(void* const* d_in, const int* in_sizes, int n_in,
                              void* d_out, int out_size) {
    const float4* in  = (const float4*)d_in[0];
    float4*       out = (float4*)d_out;
    int total4 = out_size / 4;                     // 25,165,824
    int blocks = total4 / (TPB * UNROLL);          // exact: 24,576
    dualswitch_kernel<<<blocks, TPB>>>(in, out);
}

// round 17
// speedup vs baseline: 1.0040x; 1.0040x over previous
#include <cuda_runtime.h>
#include <cstdint>

// out[b,c,i,j] = x[b,c, i^3, j^3]   (H = W = 256)
//
// FINAL (certified best: 118.848 us, reproduced twice). The reference's
// four clone+slice passes reduce to the involution idx -> idx^3 on both
// H and W. Along W, ^3 within an aligned float4 is a lane reverse; along
// H it's a row shuffle. Pure permutation copy: 805 MB mandatory traffic
// at ~6.7-6.8 TB/s (~85% of HBM spec = the measured stream ceiling).
//
// Measured design decisions (R1-R14, all axes closed):
//  - UNROLL=8 front-batched LDG.128 per thread: MLP saturation point
//    (1/4/8/16 sampled).
//  - __ldcs/__stcs streaming hints: +~3% DRAM% (zero-reuse workload).
//  - Non-persistent, consecutive-blockIdx waves: persistent grid-stride
//    regressed 10% (concurrent TLB footprint spreads across 805 MB).
//  - TPB=256 (128/512 neutral).
//  - DECOMPOSED index math: the equivalent fused `idx ^ 192` on the load
//    side regressed 2.5% (worse ptxas load-run scheduling). Keep this form.

static constexpr int W4 = 64;    // float4s per row
static constexpr int H  = 256;
static constexpr int UNROLL = 8;

__global__ void __launch_bounds__(256)
dualswitch_kernel(const float4* __restrict__ in, float4* __restrict__ out) {
    // Each block owns a contiguous chunk of 256*UNROLL float4s.
    int base = blockIdx.x * (256 * UNROLL) + threadIdx.x;

    float4 v[UNROLL];
    #pragma unroll
    for (int u = 0; u < UNROLL; u++) {
        int idx  = base + u * 256;
        int g    = idx & (W4 - 1);
        int rest = idx >> 6;
        int i    = rest & (H - 1);
        int bc   = rest >> 8;
        int in_idx = ((bc << 8) | (i ^ 3)) * W4 + g;
        v[u] = __ldcs(in + in_idx);
    }

    #pragma unroll
    for (int u = 0; u < UNROLL; u++) {
        int idx = base + u * 256;
        __stcs(out + idx, make_float4(v[u].w, v[u].z, v[u].y, v[u].x));
    }
}

extern "C" void kernel_launch(void* const* d_in, const int* in_sizes, int n_in,
                              void* d_out, int out_size) {
    const float4* in  = (const float4*)d_in[0];
    float4*       out = (float4*)d_out;
    int total4 = out_size / 4;                     // 25,165,824
    int blocks = total4 / (256 * UNROLL);          // exact: 12,288
    dualswitch_kernel<<<blocks, 256>>>(in, out);
}